// round 7
// baseline (speedup 1.0000x reference)
#include <cuda_runtime.h>
#include <cuda_bf16.h>
#include <cstdint>
#include <math.h>

// ---------------- problem constants ----------------
#define S_   2048
#define H_   2048
#define NH_  16
#define NOPE_ 128
#define ROPE_ 64
#define QHD_ 192     // NOPE+ROPE
#define VHD_ 128
#define QLR_ 1536
#define KVLR_ 512
#define FF_  8192
#define CKVD_ (KVLR_ + ROPE_)   // 576
#define QDIM_ (NH_*QHD_)        // 3072
#define KVDIM_ (NH_*(NOPE_+VHD_)) // 4096
#define SCALE_ 0.07216878364870323f  // 192^-0.5

// ---------------- scratch (static device globals; no runtime alloc) ----------------
__device__ float g_xnorm [S_*H_];
__device__ float g_qlat  [S_*QLR_];
__device__ float g_q     [S_*QDIM_];
__device__ float g_ckv   [S_*CKVD_];
__device__ float g_kvn   [S_*KVLR_];
__device__ float g_kv    [S_*KVDIM_];
__device__ float g_kpe   [S_*ROPE_];
__device__ float g_attn  [S_*H_];
__device__ float g_hid2  [S_*H_];
__device__ float g_ynorm [S_*H_];
__device__ float g_gate  [S_*FF_];
__device__ float g_up    [S_*FF_];

// ---------------- helpers ----------------
__device__ __forceinline__ float tf32r(float x) {
    uint32_t u = __float_as_uint(x), r;
    asm("cvt.rna.tf32.f32 %0, %1;" : "=r"(r) : "r"(u));
    return __uint_as_float(r);
}
__device__ __forceinline__ uint32_t tf32u(float x) {
    uint32_t u = __float_as_uint(x), r;
    asm("cvt.rna.tf32.f32 %0, %1;" : "=r"(r) : "r"(u));
    return r;
}

__device__ __forceinline__ float warp_sum(float v) {
    #pragma unroll
    for (int o = 16; o; o >>= 1) v += __shfl_xor_sync(0xffffffffu, v, o);
    return v;
}

__device__ __forceinline__ void mma_tf32(float* d, const uint32_t* a, const uint32_t* b) {
    asm volatile(
        "mma.sync.aligned.m16n8k8.row.col.f32.tf32.tf32.f32 "
        "{%0,%1,%2,%3}, {%4,%5,%6,%7}, {%8,%9}, {%0,%1,%2,%3};"
        : "+f"(d[0]), "+f"(d[1]), "+f"(d[2]), "+f"(d[3])
        : "r"(a[0]), "r"(a[1]), "r"(a[2]), "r"(a[3]), "r"(b[0]), "r"(b[1]));
}

// ---------------- rmsnorm: one block per row, tf32-rounded output ----------------
__global__ void rms_kernel(const float* __restrict__ in, const float* __restrict__ w,
                           float* __restrict__ out, int dim, int istride, int ostride) {
    int row = blockIdx.x;
    const float* x = in + (size_t)row * istride;
    float* y = out + (size_t)row * ostride;
    float s = 0.f;
    for (int i = threadIdx.x; i < dim; i += blockDim.x) { float v = x[i]; s += v * v; }
    __shared__ float red[8];
    int lane = threadIdx.x & 31, wid = threadIdx.x >> 5;
    s = warp_sum(s);
    if (lane == 0) red[wid] = s;
    __syncthreads();
    if (wid == 0) {
        float r = (lane < (int)(blockDim.x >> 5)) ? red[lane] : 0.f;
        r = warp_sum(r);
        if (lane == 0) red[0] = r;
    }
    __syncthreads();
    float inv = rsqrtf(red[0] / (float)dim + 1e-6f);
    for (int i = threadIdx.x; i < dim; i += blockDim.x) y[i] = tf32r(x[i] * inv * w[i]);
}

// ---------------- tf32 tensor-core GEMM: C = A@B (+ Cadd) ----------------
// 2-stage cp.async double buffer, 2 blocks/SM for issue-slot overlap.
#define APITCH_ 36

template<int BN>
__global__ __launch_bounds__(256, 2) void gemm_tf32(
        const float* __restrict__ A, const float* __restrict__ B,
        const float* __restrict__ Cadd, float* __restrict__ C,
        int M, int N, int K) {
    constexpr int BPITCH = BN + 8;
    constexpr int NT = BN / 16;
    constexpr int STAGE = 128 * APITCH_ + 32 * BPITCH;
    extern __shared__ float smem[];
    const int t = threadIdx.x;
    const int warp = t >> 5, lane = t & 31;
    const int wm = warp >> 1, wn = warp & 1;
    const int g = lane >> 2, t4 = lane & 3;
    const int m0 = blockIdx.y * 128, n0 = blockIdx.x * BN;

    float acc[2][NT][4] = {};

    auto load_stage = [&](int st, int kt) {
        float* as = smem + st * STAGE;
        float* bs = as + 128 * APITCH_;
        const int k0 = kt * 32;
        #pragma unroll
        for (int i = 0; i < 4; i++) {
            int id = t + i * 256;
            int row = id >> 3, c = id & 7;
            uint32_t dst = (uint32_t)__cvta_generic_to_shared(as + row * APITCH_ + c * 4);
            const float* src = A + (size_t)(m0 + row) * K + k0 + c * 4;
            asm volatile("cp.async.cg.shared.global [%0], [%1], 16;\n" :: "r"(dst), "l"(src));
        }
        #pragma unroll
        for (int i = 0; i < BN / 32; i++) {
            int id = t + i * 256;
            int row, c;
            if (BN == 128) { row = id >> 5; c = id & 31; }
            else           { row = id >> 4; c = id & 15; }
            uint32_t dst = (uint32_t)__cvta_generic_to_shared(bs + row * BPITCH + c * 4);
            const float* src = B + (size_t)(k0 + row) * N + n0 + c * 4;
            asm volatile("cp.async.cg.shared.global [%0], [%1], 16;\n" :: "r"(dst), "l"(src));
        }
        asm volatile("cp.async.commit_group;\n");
    };

    auto compute = [&](int st) {
        const float* as = smem + st * STAGE;
        const float* bs = as + 128 * APITCH_;
        #pragma unroll
        for (int ks = 0; ks < 4; ks++) {
            const int k0 = ks * 8;
            uint32_t af[2][4], bf[NT][2];
            #pragma unroll
            for (int i = 0; i < 2; i++) {
                int rbase = wm * 32 + i * 16;
                af[i][0] = __float_as_uint(as[(rbase + g    ) * APITCH_ + k0 + t4]);
                af[i][1] = __float_as_uint(as[(rbase + 8 + g) * APITCH_ + k0 + t4]);
                af[i][2] = __float_as_uint(as[(rbase + g    ) * APITCH_ + k0 + 4 + t4]);
                af[i][3] = __float_as_uint(as[(rbase + 8 + g) * APITCH_ + k0 + 4 + t4]);
            }
            #pragma unroll
            for (int j = 0; j < NT; j++) {
                int cbase = wn * (BN / 2) + j * 8 + g;
                bf[j][0] = tf32u(bs[(k0 + t4    ) * BPITCH + cbase]);
                bf[j][1] = tf32u(bs[(k0 + 4 + t4) * BPITCH + cbase]);
            }
            #pragma unroll
            for (int i = 0; i < 2; i++)
                #pragma unroll
                for (int j = 0; j < NT; j++)
                    mma_tf32(acc[i][j], af[i], bf[j]);
        }
    };

    const int nk = K / 32;
    load_stage(0, 0);
    for (int kt = 0; kt < nk; kt++) {
        asm volatile("cp.async.wait_group 0;\n");   // stage kt landed
        __syncthreads();                            // + prior compute on other stage done
        if (kt + 1 < nk) load_stage((kt + 1) & 1, kt + 1);
        compute(kt & 1);
        __syncthreads();
    }

    #pragma unroll
    for (int i = 0; i < 2; i++) {
        int r0 = m0 + wm * 32 + i * 16 + g;
        #pragma unroll
        for (int j = 0; j < NT; j++) {
            int cc = n0 + wn * (BN / 2) + j * 8 + 2 * t4;
            size_t o0 = (size_t)r0 * N + cc;
            size_t o1 = (size_t)(r0 + 8) * N + cc;
            float v0 = acc[i][j][0], v1 = acc[i][j][1];
            float v2 = acc[i][j][2], v3 = acc[i][j][3];
            if (Cadd) { v0 += Cadd[o0]; v1 += Cadd[o0 + 1]; v2 += Cadd[o1]; v3 += Cadd[o1 + 1]; }
            C[o0] = v0; C[o0 + 1] = v1; C[o1] = v2; C[o1 + 1] = v3;
        }
    }
}

#define GEMM_SMEM_128 (2 * (128*APITCH_ + 32*136) * 4)
#define GEMM_SMEM_64  (2 * (128*APITCH_ + 32*72)  * 4)

// ---------------- RoPE (interleaved permute + rotate-half) ----------------
__global__ void rope_kernel(float* __restrict__ q, const float* __restrict__ ckv,
                            float* __restrict__ kpe,
                            const float* __restrict__ cosb, const float* __restrict__ sinb,
                            const int* __restrict__ pos_ids) {
    int s = blockIdx.x;
    int pos = pos_ids[s];
    const float* c  = cosb + (size_t)pos * ROPE_;
    const float* sn = sinb + (size_t)pos * ROPE_;
    int t = threadIdx.x;
    float ox[4], oy[4];
    #pragma unroll
    for (int it = 0; it < 4; it++) {
        int item = t + it * 128;
        int h = item >> 5, i = item & 31;
        float* base = q + (size_t)s * QDIM_ + h * QHD_ + NOPE_;
        float x0 = base[2 * i], x1 = base[2 * i + 1];
        ox[it] = x0 * c[i]      - x1 * sn[i];
        oy[it] = x1 * c[i + 32] + x0 * sn[i + 32];
    }
    __syncthreads();
    #pragma unroll
    for (int it = 0; it < 4; it++) {
        int item = t + it * 128;
        int h = item >> 5, i = item & 31;
        float* base = q + (size_t)s * QDIM_ + h * QHD_ + NOPE_;
        base[i]      = ox[it];
        base[i + 32] = oy[it];
    }
    if (t < 32) {
        const float* kb = ckv + (size_t)s * CKVD_ + KVLR_;
        float x0 = kb[2 * t], x1 = kb[2 * t + 1];
        kpe[(size_t)s * ROPE_ + t]      = x0 * c[t]      - x1 * sn[t];
        kpe[(size_t)s * ROPE_ + 32 + t] = x1 * c[t + 32] + x0 * sn[t + 32];
    }
}

// ---------------- tensor-core causal flash attention (tf32 mma) ----------------
#define QP_ 196
#define KP_ 196
#define VP_ 136
#define PP_ 68
#define ATT_SMEM_FLOATS (64*QP_ + 64*KP_ + 64*VP_ + 64*PP_)

__global__ __launch_bounds__(128, 1) void attn_mma_kernel(
        const float* __restrict__ q, const float* __restrict__ kv,
        const float* __restrict__ kpe, float* __restrict__ out) {
    extern __shared__ float smem[];
    float* qs = smem;                 // [64][QP_]
    float* ks = qs + 64 * QP_;        // [64][KP_]
    float* vs = ks + 64 * KP_;        // [64][VP_]
    float* ps = vs + 64 * VP_;        // [64][PP_]

    const int h = blockIdx.y;
    const int qblk = (int)gridDim.x - 1 - (int)blockIdx.x;
    const int t = threadIdx.x;
    const int warp = t >> 5, lane = t & 31;
    const int g = lane >> 2, t4 = lane & 3;
    const int qbase = qblk * 64;
    const int wrow = warp * 16;

    for (int idx = t * 4; idx < 64 * 192; idx += 128 * 4) {
        int row = idx / 192, col = idx - row * 192;
        float4 v = *(const float4*)&q[(size_t)(qbase + row) * QDIM_ + h * QHD_ + col];
        *(float4*)&qs[row * QP_ + col] = v;
    }

    float oa[16][4];
    #pragma unroll
    for (int j = 0; j < 16; j++)
        #pragma unroll
        for (int c = 0; c < 4; c++) oa[j][c] = 0.f;
    float m0 = -1e30f, m1 = -1e30f, l0 = 0.f, l1 = 0.f;

    for (int kt = 0; kt <= qblk; kt++) {
        const int kbase = kt * 64;
        __syncthreads();
        for (int idx = t * 4; idx < 64 * 192; idx += 128 * 4) {
            int row = idx / 192, col = idx - row * 192;
            int key = kbase + row;
            float4 v = (col < 128)
                ? *(const float4*)&kv[(size_t)key * KVDIM_ + h * 256 + col]
                : *(const float4*)&kpe[(size_t)key * ROPE_ + (col - 128)];
            *(float4*)&ks[row * KP_ + col] = v;
        }
        for (int idx = t * 4; idx < 64 * 128; idx += 128 * 4) {
            int row = idx >> 7, col = idx & 127;
            float4 v = *(const float4*)&kv[(size_t)(kbase + row) * KVDIM_ + h * 256 + 128 + col];
            *(float4*)&vs[row * VP_ + col] = v;
        }
        __syncthreads();

        float sa[8][4];
        #pragma unroll
        for (int j = 0; j < 8; j++)
            #pragma unroll
            for (int c = 0; c < 4; c++) sa[j][c] = 0.f;
        #pragma unroll
        for (int kc = 0; kc < 24; kc++) {
            const int k0 = kc * 8;
            uint32_t af[4], bf[8][2];
            af[0] = __float_as_uint(qs[(wrow + g    ) * QP_ + k0 + t4]);
            af[1] = __float_as_uint(qs[(wrow + 8 + g) * QP_ + k0 + t4]);
            af[2] = __float_as_uint(qs[(wrow + g    ) * QP_ + k0 + 4 + t4]);
            af[3] = __float_as_uint(qs[(wrow + 8 + g) * QP_ + k0 + 4 + t4]);
            #pragma unroll
            for (int j = 0; j < 8; j++) {
                bf[j][0] = __float_as_uint(ks[(j * 8 + g) * KP_ + k0 + t4]);
                bf[j][1] = __float_as_uint(ks[(j * 8 + g) * KP_ + k0 + 4 + t4]);
            }
            #pragma unroll
            for (int j = 0; j < 8; j++) mma_tf32(sa[j], af, bf[j]);
        }

        const int r0 = qbase + wrow + g;
        const int r1 = r0 + 8;
        const bool diag = (kt == qblk);
        #pragma unroll
        for (int j = 0; j < 8; j++) {
            int c0 = kbase + j * 8 + 2 * t4, c1 = c0 + 1;
            sa[j][0] *= SCALE_; sa[j][1] *= SCALE_;
            sa[j][2] *= SCALE_; sa[j][3] *= SCALE_;
            if (diag) {
                if (c0 > r0) sa[j][0] = -1e30f;
                if (c1 > r0) sa[j][1] = -1e30f;
                if (c0 > r1) sa[j][2] = -1e30f;
                if (c1 > r1) sa[j][3] = -1e30f;
            }
        }

        float tm0 = -1e30f, tm1 = -1e30f;
        #pragma unroll
        for (int j = 0; j < 8; j++) {
            tm0 = fmaxf(tm0, fmaxf(sa[j][0], sa[j][1]));
            tm1 = fmaxf(tm1, fmaxf(sa[j][2], sa[j][3]));
        }
        tm0 = fmaxf(tm0, __shfl_xor_sync(0xffffffffu, tm0, 1));
        tm0 = fmaxf(tm0, __shfl_xor_sync(0xffffffffu, tm0, 2));
        tm1 = fmaxf(tm1, __shfl_xor_sync(0xffffffffu, tm1, 1));
        tm1 = fmaxf(tm1, __shfl_xor_sync(0xffffffffu, tm1, 2));
        float m0n = fmaxf(m0, tm0), m1n = fmaxf(m1, tm1);
        float a0 = __expf(m0 - m0n), a1 = __expf(m1 - m1n);
        float ps0 = 0.f, ps1 = 0.f;
        #pragma unroll
        for (int j = 0; j < 8; j++) {
            sa[j][0] = __expf(sa[j][0] - m0n); sa[j][1] = __expf(sa[j][1] - m0n);
            sa[j][2] = __expf(sa[j][2] - m1n); sa[j][3] = __expf(sa[j][3] - m1n);
            ps0 += sa[j][0] + sa[j][1];
            ps1 += sa[j][2] + sa[j][3];
        }
        ps0 += __shfl_xor_sync(0xffffffffu, ps0, 1);
        ps0 += __shfl_xor_sync(0xffffffffu, ps0, 2);
        ps1 += __shfl_xor_sync(0xffffffffu, ps1, 1);
        ps1 += __shfl_xor_sync(0xffffffffu, ps1, 2);
        l0 = l0 * a0 + ps0; l1 = l1 * a1 + ps1;
        m0 = m0n; m1 = m1n;
        #pragma unroll
        for (int j = 0; j < 16; j++) {
            oa[j][0] *= a0; oa[j][1] *= a0;
            oa[j][2] *= a1; oa[j][3] *= a1;
        }
        #pragma unroll
        for (int j = 0; j < 8; j++) {
            int cc = j * 8 + 2 * t4;
            ps[(wrow + g    ) * PP_ + cc]     = sa[j][0];
            ps[(wrow + g    ) * PP_ + cc + 1] = sa[j][1];
            ps[(wrow + 8 + g) * PP_ + cc]     = sa[j][2];
            ps[(wrow + 8 + g) * PP_ + cc + 1] = sa[j][3];
        }
        __syncwarp();

        #pragma unroll
        for (int kc = 0; kc < 8; kc++) {
            const int k0 = kc * 8;
            uint32_t af[4], bf[16][2];
            af[0] = __float_as_uint(ps[(wrow + g    ) * PP_ + k0 + t4]);
            af[1] = __float_as_uint(ps[(wrow + 8 + g) * PP_ + k0 + t4]);
            af[2] = __float_as_uint(ps[(wrow + g    ) * PP_ + k0 + 4 + t4]);
            af[3] = __float_as_uint(ps[(wrow + 8 + g) * PP_ + k0 + 4 + t4]);
            #pragma unroll
            for (int j = 0; j < 16; j++) {
                bf[j][0] = __float_as_uint(vs[(k0 + t4    ) * VP_ + j * 8 + g]);
                bf[j][1] = __float_as_uint(vs[(k0 + 4 + t4) * VP_ + j * 8 + g]);
            }
            #pragma unroll
            for (int j = 0; j < 16; j++) mma_tf32(oa[j], af, bf[j]);
        }
    }

    float i0 = 1.f / l0, i1 = 1.f / l1;
    const int r0 = qbase + wrow + g;
    float* o0 = out + (size_t)r0 * H_ + h * VHD_;
    float* o1 = out + (size_t)(r0 + 8) * H_ + h * VHD_;
    #pragma unroll
    for (int j = 0; j < 16; j++) {
        int cc = j * 8 + 2 * t4;
        o0[cc]     = tf32r(oa[j][0] * i0);
        o0[cc + 1] = tf32r(oa[j][1] * i0);
        o1[cc]     = tf32r(oa[j][2] * i1);
        o1[cc + 1] = tf32r(oa[j][3] * i1);
    }
}

// ---------------- silu(gate) * up, in place into gate (tf32-rounded) ----------------
__global__ void silu_mul_kernel(float* __restrict__ g, const float* __restrict__ u, int n) {
    int i = blockIdx.x * blockDim.x + threadIdx.x;
    if (i < n) {
        float x = g[i];
        float s = x / (1.f + __expf(-x));
        g[i] = tf32r(s * u[i]);
    }
}

// ---------------- launcher ----------------
extern "C" void kernel_launch(void* const* d_in, const int* in_sizes, int n_in,
                              void* d_out, int out_size) {
    const float* hidden  = (const float*)d_in[0];
    const float* sinb    = (const float*)d_in[1];
    const float* cosb    = (const float*)d_in[2];
    const float* wq_a    = (const float*)d_in[3];
    const float* q_a_ln  = (const float*)d_in[4];
    const float* wq_b    = (const float*)d_in[5];
    const float* wkv_a   = (const float*)d_in[6];
    const float* kv_a_ln = (const float*)d_in[7];
    const float* wkv_b   = (const float*)d_in[8];
    const float* wo      = (const float*)d_in[9];
    const float* in_ln   = (const float*)d_in[10];
    const float* post_ln = (const float*)d_in[11];
    const float* w_gate  = (const float*)d_in[12];
    const float* w_up    = (const float*)d_in[13];
    const float* w_down  = (const float*)d_in[14];
    const int*   pos     = (const int*)d_in[15];
    float* outp = (float*)d_out;

    float *xnorm, *qlat, *qb, *ckv, *kvn, *kvb, *kpe, *attn, *hid2, *ynorm, *gate, *up;
    cudaGetSymbolAddress((void**)&xnorm, g_xnorm);
    cudaGetSymbolAddress((void**)&qlat,  g_qlat);
    cudaGetSymbolAddress((void**)&qb,    g_q);
    cudaGetSymbolAddress((void**)&ckv,   g_ckv);
    cudaGetSymbolAddress((void**)&kvn,   g_kvn);
    cudaGetSymbolAddress((void**)&kvb,   g_kv);
    cudaGetSymbolAddress((void**)&kpe,   g_kpe);
    cudaGetSymbolAddress((void**)&attn,  g_attn);
    cudaGetSymbolAddress((void**)&hid2,  g_hid2);
    cudaGetSymbolAddress((void**)&ynorm, g_ynorm);
    cudaGetSymbolAddress((void**)&gate,  g_gate);
    cudaGetSymbolAddress((void**)&up,    g_up);

    const size_t attn_smem = ATT_SMEM_FLOATS * sizeof(float);
    cudaFuncSetAttribute(attn_mma_kernel, cudaFuncAttributeMaxDynamicSharedMemorySize, (int)attn_smem);
    cudaFuncSetAttribute(gemm_tf32<128>, cudaFuncAttributeMaxDynamicSharedMemorySize, GEMM_SMEM_128);
    cudaFuncSetAttribute(gemm_tf32<64>,  cudaFuncAttributeMaxDynamicSharedMemorySize, GEMM_SMEM_64);

    dim3 blk256(256);
    auto gemm128 = [&](const float* A, const float* B, const float* Cadd, float* C,
                       int M, int N, int K) {
        gemm_tf32<128><<<dim3(N / 128, M / 128), blk256, GEMM_SMEM_128>>>(A, B, Cadd, C, M, N, K);
    };
    auto gemm64 = [&](const float* A, const float* B, const float* Cadd, float* C,
                      int M, int N, int K) {
        gemm_tf32<64><<<dim3(N / 64, M / 128), blk256, GEMM_SMEM_64>>>(A, B, Cadd, C, M, N, K);
    };

    // 1) x = rms(hidden, in_ln)
    rms_kernel<<<S_, 256>>>(hidden, in_ln, xnorm, H_, H_, H_);
    // 2) q_lat = x @ wq_a
    gemm128(xnorm, wq_a, nullptr, qlat, S_, QLR_, H_);
    // 3) q_lat = rms(q_lat, q_a_ln)
    rms_kernel<<<S_, 256>>>(qlat, q_a_ln, qlat, QLR_, QLR_, QLR_);
    // 4) q = q_lat @ wq_b
    gemm128(qlat, wq_b, nullptr, qb, S_, QDIM_, QLR_);
    // 5) ckv = x @ wkv_a
    gemm64(xnorm, wkv_a, nullptr, ckv, S_, CKVD_, H_);
    // 6) kv_n = rms(ckv[:, :512], kv_a_ln)
    rms_kernel<<<S_, 256>>>(ckv, kv_a_ln, kvn, KVLR_, CKVD_, KVLR_);
    // 7) kv = kv_n @ wkv_b
    gemm128(kvn, wkv_b, nullptr, kvb, S_, KVDIM_, KVLR_);
    // 8) RoPE
    rope_kernel<<<S_, 128>>>(qb, ckv, kpe, cosb, sinb, pos);
    // 9) attention (tensor-core flash)
    attn_mma_kernel<<<dim3(S_/64, NH_), 128, attn_smem>>>(qb, kvb, kpe, attn);
    // 10) hid2 = hidden + attn @ wo
    gemm128(attn, wo, hidden, hid2, S_, H_, H_);
    // 11) y = rms(hid2, post_ln)
    rms_kernel<<<S_, 256>>>(hid2, post_ln, ynorm, H_, H_, H_);
    // 12) gate = y @ w_gate
    gemm128(ynorm, w_gate, nullptr, gate, S_, FF_, H_);
    // 13) up = y @ w_up
    gemm128(ynorm, w_up, nullptr, up, S_, FF_, H_);
    // 14) gate = silu(gate) * up
    {
        int n = S_ * FF_;
        silu_mul_kernel<<<(n + 255) / 256, 256>>>(gate, up, n);
    }
    // 15) out = hid2 + gate @ w_down
    gemm128(gate, w_down, hid2, outp, S_, H_, FF_);
}

// round 8
// speedup vs baseline: 1.0779x; 1.0779x over previous
#include <cuda_runtime.h>
#include <cuda_bf16.h>
#include <cstdint>
#include <math.h>

// ---------------- problem constants ----------------
#define S_   2048
#define H_   2048
#define NH_  16
#define NOPE_ 128
#define ROPE_ 64
#define QHD_ 192     // NOPE+ROPE
#define VHD_ 128
#define QLR_ 1536
#define KVLR_ 512
#define FF_  8192
#define CKVD_ (KVLR_ + ROPE_)   // 576
#define QDIM_ (NH_*QHD_)        // 3072
#define KVDIM_ (NH_*(NOPE_+VHD_)) // 4096
#define SCALE_ 0.07216878364870323f  // 192^-0.5

// ---------------- scratch (static device globals; no runtime alloc) ----------------
__device__ float g_xnorm [S_*H_];
__device__ float g_qlat  [S_*QLR_];
__device__ float g_q     [S_*QDIM_];
__device__ float g_ckv   [S_*CKVD_];
__device__ float g_kvn   [S_*KVLR_];
__device__ float g_kv    [S_*KVDIM_];
__device__ float g_kpe   [S_*ROPE_];
__device__ float g_attn  [S_*H_];
__device__ float g_hid2  [S_*H_];
__device__ float g_ynorm [S_*H_];
__device__ float g_gate  [S_*FF_];
__device__ float g_up    [S_*FF_];

// ---------------- helpers ----------------
__device__ __forceinline__ float tf32r(float x) {
    uint32_t u = __float_as_uint(x), r;
    asm("cvt.rna.tf32.f32 %0, %1;" : "=r"(r) : "r"(u));
    return __uint_as_float(r);
}
__device__ __forceinline__ uint32_t tf32u(float x) {
    uint32_t u = __float_as_uint(x), r;
    asm("cvt.rna.tf32.f32 %0, %1;" : "=r"(r) : "r"(u));
    return r;
}

__device__ __forceinline__ float warp_sum(float v) {
    #pragma unroll
    for (int o = 16; o; o >>= 1) v += __shfl_xor_sync(0xffffffffu, v, o);
    return v;
}

__device__ __forceinline__ void mma_tf32(float* d, const uint32_t* a, const uint32_t* b) {
    asm volatile(
        "mma.sync.aligned.m16n8k8.row.col.f32.tf32.tf32.f32 "
        "{%0,%1,%2,%3}, {%4,%5,%6,%7}, {%8,%9}, {%0,%1,%2,%3};"
        : "+f"(d[0]), "+f"(d[1]), "+f"(d[2]), "+f"(d[3])
        : "r"(a[0]), "r"(a[1]), "r"(a[2]), "r"(a[3]), "r"(b[0]), "r"(b[1]));
}

// ---------------- rmsnorm: one block per row, tf32-rounded output ----------------
__global__ void rms_kernel(const float* __restrict__ in, const float* __restrict__ w,
                           float* __restrict__ out, int dim, int istride, int ostride) {
    int row = blockIdx.x;
    const float* x = in + (size_t)row * istride;
    float* y = out + (size_t)row * ostride;
    float s = 0.f;
    for (int i = threadIdx.x; i < dim; i += blockDim.x) { float v = x[i]; s += v * v; }
    __shared__ float red[8];
    int lane = threadIdx.x & 31, wid = threadIdx.x >> 5;
    s = warp_sum(s);
    if (lane == 0) red[wid] = s;
    __syncthreads();
    if (wid == 0) {
        float r = (lane < (int)(blockDim.x >> 5)) ? red[lane] : 0.f;
        r = warp_sum(r);
        if (lane == 0) red[0] = r;
    }
    __syncthreads();
    float inv = rsqrtf(red[0] / (float)dim + 1e-6f);
    for (int i = threadIdx.x; i < dim; i += blockDim.x) y[i] = tf32r(x[i] * inv * w[i]);
}

// ============ main tf32 GEMM: block 128x128, 4 warps of 64x64, 3-stage ============
// A [M,K] row-major (tf32-rounded), B [K,N] raw fp32 (rounded in-register).
// M%128==0, N%128==0, K%32==0.
#define APITCH_ 36
#define BPITCH2_ 136
#define STAGE2_ (128*APITCH_ + 32*BPITCH2_)    // 8960 floats
#define GEMM2_SMEM (3*STAGE2_*4)               // 107,520 B

__global__ __launch_bounds__(128, 2) void gemm_tf32_big(
        const float* __restrict__ A, const float* __restrict__ B,
        const float* __restrict__ Cadd, float* __restrict__ C,
        int M, int N, int K) {
    extern __shared__ float smem[];
    const int t = threadIdx.x;
    const int warp = t >> 5, lane = t & 31;
    const int wm = warp >> 1, wn = warp & 1;   // 2x2 warps, each 64x64
    const int g = lane >> 2, t4 = lane & 3;
    const int m0 = blockIdx.y * 128, n0 = blockIdx.x * 128;

    float acc[4][8][4] = {};

    auto load_stage = [&](int st, int kt) {
        float* as = smem + st * STAGE2_;
        float* bs = as + 128 * APITCH_;
        const int k0 = kt * 32;
        #pragma unroll
        for (int i = 0; i < 8; i++) {           // A: 128x32 = 1024 16B chunks
            int id = t + i * 128;
            int row = id >> 3, c = id & 7;
            uint32_t dst = (uint32_t)__cvta_generic_to_shared(as + row * APITCH_ + c * 4);
            const float* src = A + (size_t)(m0 + row) * K + k0 + c * 4;
            asm volatile("cp.async.cg.shared.global [%0], [%1], 16;\n" :: "r"(dst), "l"(src));
        }
        #pragma unroll
        for (int i = 0; i < 8; i++) {           // B: 32x128 = 1024 16B chunks
            int id = t + i * 128;
            int row = id >> 5, c = id & 31;
            uint32_t dst = (uint32_t)__cvta_generic_to_shared(bs + row * BPITCH2_ + c * 4);
            const float* src = B + (size_t)(k0 + row) * N + n0 + c * 4;
            asm volatile("cp.async.cg.shared.global [%0], [%1], 16;\n" :: "r"(dst), "l"(src));
        }
        asm volatile("cp.async.commit_group;\n");
    };

    auto compute = [&](int st) {
        const float* as = smem + st * STAGE2_;
        const float* bs = as + 128 * APITCH_;
        #pragma unroll
        for (int ks = 0; ks < 4; ks++) {
            const int k0 = ks * 8;
            uint32_t bf[8][2];
            #pragma unroll
            for (int j = 0; j < 8; j++) {
                int cbase = wn * 64 + j * 8 + g;
                bf[j][0] = tf32u(bs[(k0 + t4    ) * BPITCH2_ + cbase]);
                bf[j][1] = tf32u(bs[(k0 + 4 + t4) * BPITCH2_ + cbase]);
            }
            #pragma unroll
            for (int i = 0; i < 4; i++) {
                uint32_t af[4];
                int rbase = wm * 64 + i * 16;
                af[0] = __float_as_uint(as[(rbase + g    ) * APITCH_ + k0 + t4]);
                af[1] = __float_as_uint(as[(rbase + 8 + g) * APITCH_ + k0 + t4]);
                af[2] = __float_as_uint(as[(rbase + g    ) * APITCH_ + k0 + 4 + t4]);
                af[3] = __float_as_uint(as[(rbase + 8 + g) * APITCH_ + k0 + 4 + t4]);
                #pragma unroll
                for (int j = 0; j < 8; j++)
                    mma_tf32(acc[i][j], af, bf[j]);
            }
        }
    };

    const int nk = K / 32;
    load_stage(0, 0);
    if (nk > 1) load_stage(1, 1);

    int st_load = 2, st_comp = 0;
    for (int kt = 0; kt < nk; kt++) {
        if (kt + 2 <= nk) { asm volatile("cp.async.wait_group 1;\n"); }
        else              { asm volatile("cp.async.wait_group 0;\n"); }
        __syncthreads();
        if (kt + 2 < nk) {
            load_stage(st_load, kt + 2);
            st_load = (st_load == 2) ? 0 : st_load + 1;
        }
        compute(st_comp);
        st_comp = (st_comp == 2) ? 0 : st_comp + 1;
        __syncthreads();
    }

    // epilogue
    #pragma unroll
    for (int i = 0; i < 4; i++) {
        int r0 = m0 + wm * 64 + i * 16 + g;
        #pragma unroll
        for (int j = 0; j < 8; j++) {
            int cc = n0 + wn * 64 + j * 8 + 2 * t4;
            size_t o0 = (size_t)r0 * N + cc;
            size_t o1 = (size_t)(r0 + 8) * N + cc;
            float v0 = acc[i][j][0], v1 = acc[i][j][1];
            float v2 = acc[i][j][2], v3 = acc[i][j][3];
            if (Cadd) { v0 += Cadd[o0]; v1 += Cadd[o0 + 1]; v2 += Cadd[o1]; v3 += Cadd[o1 + 1]; }
            C[o0] = v0; C[o0 + 1] = v1; C[o1] = v2; C[o1 + 1] = v3;
        }
    }
}

// ============ small-N tf32 GEMM (BN=64): block 128x64, 8 warps of 32x32 ============
template<int BN>
__global__ __launch_bounds__(256, 2) void gemm_tf32(
        const float* __restrict__ A, const float* __restrict__ B,
        const float* __restrict__ Cadd, float* __restrict__ C,
        int M, int N, int K) {
    constexpr int BPITCH = BN + 8;
    constexpr int NT = BN / 16;
    constexpr int STAGE = 128 * APITCH_ + 32 * BPITCH;
    extern __shared__ float smem[];
    const int t = threadIdx.x;
    const int warp = t >> 5, lane = t & 31;
    const int wm = warp >> 1, wn = warp & 1;
    const int g = lane >> 2, t4 = lane & 3;
    const int m0 = blockIdx.y * 128, n0 = blockIdx.x * BN;

    float acc[2][NT][4] = {};

    auto load_stage = [&](int st, int kt) {
        float* as = smem + st * STAGE;
        float* bs = as + 128 * APITCH_;
        const int k0 = kt * 32;
        #pragma unroll
        for (int i = 0; i < 4; i++) {
            int id = t + i * 256;
            int row = id >> 3, c = id & 7;
            uint32_t dst = (uint32_t)__cvta_generic_to_shared(as + row * APITCH_ + c * 4);
            const float* src = A + (size_t)(m0 + row) * K + k0 + c * 4;
            asm volatile("cp.async.cg.shared.global [%0], [%1], 16;\n" :: "r"(dst), "l"(src));
        }
        #pragma unroll
        for (int i = 0; i < BN / 32; i++) {
            int id = t + i * 256;
            int row = id >> 4, c = id & 15;
            uint32_t dst = (uint32_t)__cvta_generic_to_shared(bs + row * BPITCH + c * 4);
            const float* src = B + (size_t)(k0 + row) * N + n0 + c * 4;
            asm volatile("cp.async.cg.shared.global [%0], [%1], 16;\n" :: "r"(dst), "l"(src));
        }
        asm volatile("cp.async.commit_group;\n");
    };

    auto compute = [&](int st) {
        const float* as = smem + st * STAGE;
        const float* bs = as + 128 * APITCH_;
        #pragma unroll
        for (int ks = 0; ks < 4; ks++) {
            const int k0 = ks * 8;
            uint32_t af[2][4], bf[NT][2];
            #pragma unroll
            for (int i = 0; i < 2; i++) {
                int rbase = wm * 32 + i * 16;
                af[i][0] = __float_as_uint(as[(rbase + g    ) * APITCH_ + k0 + t4]);
                af[i][1] = __float_as_uint(as[(rbase + 8 + g) * APITCH_ + k0 + t4]);
                af[i][2] = __float_as_uint(as[(rbase + g    ) * APITCH_ + k0 + 4 + t4]);
                af[i][3] = __float_as_uint(as[(rbase + 8 + g) * APITCH_ + k0 + 4 + t4]);
            }
            #pragma unroll
            for (int j = 0; j < NT; j++) {
                int cbase = wn * (BN / 2) + j * 8 + g;
                bf[j][0] = tf32u(bs[(k0 + t4    ) * BPITCH + cbase]);
                bf[j][1] = tf32u(bs[(k0 + 4 + t4) * BPITCH + cbase]);
            }
            #pragma unroll
            for (int i = 0; i < 2; i++)
                #pragma unroll
                for (int j = 0; j < NT; j++)
                    mma_tf32(acc[i][j], af[i], bf[j]);
        }
    };

    const int nk = K / 32;
    load_stage(0, 0);
    for (int kt = 0; kt < nk; kt++) {
        asm volatile("cp.async.wait_group 0;\n");
        __syncthreads();
        if (kt + 1 < nk) load_stage((kt + 1) & 1, kt + 1);
        compute(kt & 1);
        __syncthreads();
    }

    #pragma unroll
    for (int i = 0; i < 2; i++) {
        int r0 = m0 + wm * 32 + i * 16 + g;
        #pragma unroll
        for (int j = 0; j < NT; j++) {
            int cc = n0 + wn * (BN / 2) + j * 8 + 2 * t4;
            size_t o0 = (size_t)r0 * N + cc;
            size_t o1 = (size_t)(r0 + 8) * N + cc;
            float v0 = acc[i][j][0], v1 = acc[i][j][1];
            float v2 = acc[i][j][2], v3 = acc[i][j][3];
            if (Cadd) { v0 += Cadd[o0]; v1 += Cadd[o0 + 1]; v2 += Cadd[o1]; v3 += Cadd[o1 + 1]; }
            C[o0] = v0; C[o0 + 1] = v1; C[o1] = v2; C[o1 + 1] = v3;
        }
    }
}

#define GEMM_SMEM_64  (2 * (128*APITCH_ + 32*72) * 4)

// ---------------- RoPE (interleaved permute + rotate-half) ----------------
__global__ void rope_kernel(float* __restrict__ q, const float* __restrict__ ckv,
                            float* __restrict__ kpe,
                            const float* __restrict__ cosb, const float* __restrict__ sinb,
                            const int* __restrict__ pos_ids) {
    int s = blockIdx.x;
    int pos = pos_ids[s];
    const float* c  = cosb + (size_t)pos * ROPE_;
    const float* sn = sinb + (size_t)pos * ROPE_;
    int t = threadIdx.x;
    float ox[4], oy[4];
    #pragma unroll
    for (int it = 0; it < 4; it++) {
        int item = t + it * 128;
        int h = item >> 5, i = item & 31;
        float* base = q + (size_t)s * QDIM_ + h * QHD_ + NOPE_;
        float x0 = base[2 * i], x1 = base[2 * i + 1];
        ox[it] = x0 * c[i]      - x1 * sn[i];
        oy[it] = x1 * c[i + 32] + x0 * sn[i + 32];
    }
    __syncthreads();
    #pragma unroll
    for (int it = 0; it < 4; it++) {
        int item = t + it * 128;
        int h = item >> 5, i = item & 31;
        float* base = q + (size_t)s * QDIM_ + h * QHD_ + NOPE_;
        base[i]      = ox[it];
        base[i + 32] = oy[it];
    }
    if (t < 32) {
        const float* kb = ckv + (size_t)s * CKVD_ + KVLR_;
        float x0 = kb[2 * t], x1 = kb[2 * t + 1];
        kpe[(size_t)s * ROPE_ + t]      = x0 * c[t]      - x1 * sn[t];
        kpe[(size_t)s * ROPE_ + 32 + t] = x1 * c[t + 32] + x0 * sn[t + 32];
    }
}

// ---------------- tensor-core causal flash attention (tf32 mma) ----------------
#define QP_ 196
#define KP_ 196
#define VP_ 136
#define PP_ 68
#define ATT_SMEM_FLOATS (64*QP_ + 64*KP_ + 64*VP_ + 64*PP_)

__global__ __launch_bounds__(128, 1) void attn_mma_kernel(
        const float* __restrict__ q, const float* __restrict__ kv,
        const float* __restrict__ kpe, float* __restrict__ out) {
    extern __shared__ float smem[];
    float* qs = smem;                 // [64][QP_]
    float* ks = qs + 64 * QP_;        // [64][KP_]
    float* vs = ks + 64 * KP_;        // [64][VP_]
    float* ps = vs + 64 * VP_;        // [64][PP_]

    const int h = blockIdx.y;
    const int qblk = (int)gridDim.x - 1 - (int)blockIdx.x;
    const int t = threadIdx.x;
    const int warp = t >> 5, lane = t & 31;
    const int g = lane >> 2, t4 = lane & 3;
    const int qbase = qblk * 64;
    const int wrow = warp * 16;

    for (int idx = t * 4; idx < 64 * 192; idx += 128 * 4) {
        int row = idx / 192, col = idx - row * 192;
        float4 v = *(const float4*)&q[(size_t)(qbase + row) * QDIM_ + h * QHD_ + col];
        *(float4*)&qs[row * QP_ + col] = v;
    }

    float oa[16][4];
    #pragma unroll
    for (int j = 0; j < 16; j++)
        #pragma unroll
        for (int c = 0; c < 4; c++) oa[j][c] = 0.f;
    float m0 = -1e30f, m1 = -1e30f, l0 = 0.f, l1 = 0.f;

    for (int kt = 0; kt <= qblk; kt++) {
        const int kbase = kt * 64;
        __syncthreads();
        for (int idx = t * 4; idx < 64 * 192; idx += 128 * 4) {
            int row = idx / 192, col = idx - row * 192;
            int key = kbase + row;
            float4 v = (col < 128)
                ? *(const float4*)&kv[(size_t)key * KVDIM_ + h * 256 + col]
                : *(const float4*)&kpe[(size_t)key * ROPE_ + (col - 128)];
            *(float4*)&ks[row * KP_ + col] = v;
        }
        for (int idx = t * 4; idx < 64 * 128; idx += 128 * 4) {
            int row = idx >> 7, col = idx & 127;
            float4 v = *(const float4*)&kv[(size_t)(kbase + row) * KVDIM_ + h * 256 + 128 + col];
            *(float4*)&vs[row * VP_ + col] = v;
        }
        __syncthreads();

        float sa[8][4];
        #pragma unroll
        for (int j = 0; j < 8; j++)
            #pragma unroll
            for (int c = 0; c < 4; c++) sa[j][c] = 0.f;
        #pragma unroll
        for (int kc = 0; kc < 24; kc++) {
            const int k0 = kc * 8;
            uint32_t af[4], bf[8][2];
            af[0] = __float_as_uint(qs[(wrow + g    ) * QP_ + k0 + t4]);
            af[1] = __float_as_uint(qs[(wrow + 8 + g) * QP_ + k0 + t4]);
            af[2] = __float_as_uint(qs[(wrow + g    ) * QP_ + k0 + 4 + t4]);
            af[3] = __float_as_uint(qs[(wrow + 8 + g) * QP_ + k0 + 4 + t4]);
            #pragma unroll
            for (int j = 0; j < 8; j++) {
                bf[j][0] = __float_as_uint(ks[(j * 8 + g) * KP_ + k0 + t4]);
                bf[j][1] = __float_as_uint(ks[(j * 8 + g) * KP_ + k0 + 4 + t4]);
            }
            #pragma unroll
            for (int j = 0; j < 8; j++) mma_tf32(sa[j], af, bf[j]);
        }

        const int r0 = qbase + wrow + g;
        const int r1 = r0 + 8;
        const bool diag = (kt == qblk);
        #pragma unroll
        for (int j = 0; j < 8; j++) {
            int c0 = kbase + j * 8 + 2 * t4, c1 = c0 + 1;
            sa[j][0] *= SCALE_; sa[j][1] *= SCALE_;
            sa[j][2] *= SCALE_; sa[j][3] *= SCALE_;
            if (diag) {
                if (c0 > r0) sa[j][0] = -1e30f;
                if (c1 > r0) sa[j][1] = -1e30f;
                if (c0 > r1) sa[j][2] = -1e30f;
                if (c1 > r1) sa[j][3] = -1e30f;
            }
        }

        float tm0 = -1e30f, tm1 = -1e30f;
        #pragma unroll
        for (int j = 0; j < 8; j++) {
            tm0 = fmaxf(tm0, fmaxf(sa[j][0], sa[j][1]));
            tm1 = fmaxf(tm1, fmaxf(sa[j][2], sa[j][3]));
        }
        tm0 = fmaxf(tm0, __shfl_xor_sync(0xffffffffu, tm0, 1));
        tm0 = fmaxf(tm0, __shfl_xor_sync(0xffffffffu, tm0, 2));
        tm1 = fmaxf(tm1, __shfl_xor_sync(0xffffffffu, tm1, 1));
        tm1 = fmaxf(tm1, __shfl_xor_sync(0xffffffffu, tm1, 2));
        float m0n = fmaxf(m0, tm0), m1n = fmaxf(m1, tm1);
        float a0 = __expf(m0 - m0n), a1 = __expf(m1 - m1n);
        float ps0 = 0.f, ps1 = 0.f;
        #pragma unroll
        for (int j = 0; j < 8; j++) {
            sa[j][0] = __expf(sa[j][0] - m0n); sa[j][1] = __expf(sa[j][1] - m0n);
            sa[j][2] = __expf(sa[j][2] - m1n); sa[j][3] = __expf(sa[j][3] - m1n);
            ps0 += sa[j][0] + sa[j][1];
            ps1 += sa[j][2] + sa[j][3];
        }
        ps0 += __shfl_xor_sync(0xffffffffu, ps0, 1);
        ps0 += __shfl_xor_sync(0xffffffffu, ps0, 2);
        ps1 += __shfl_xor_sync(0xffffffffu, ps1, 1);
        ps1 += __shfl_xor_sync(0xffffffffu, ps1, 2);
        l0 = l0 * a0 + ps0; l1 = l1 * a1 + ps1;
        m0 = m0n; m1 = m1n;
        #pragma unroll
        for (int j = 0; j < 16; j++) {
            oa[j][0] *= a0; oa[j][1] *= a0;
            oa[j][2] *= a1; oa[j][3] *= a1;
        }
        #pragma unroll
        for (int j = 0; j < 8; j++) {
            int cc = j * 8 + 2 * t4;
            ps[(wrow + g    ) * PP_ + cc]     = sa[j][0];
            ps[(wrow + g    ) * PP_ + cc + 1] = sa[j][1];
            ps[(wrow + 8 + g) * PP_ + cc]     = sa[j][2];
            ps[(wrow + 8 + g) * PP_ + cc + 1] = sa[j][3];
        }
        __syncwarp();

        #pragma unroll
        for (int kc = 0; kc < 8; kc++) {
            const int k0 = kc * 8;
            uint32_t af[4], bf[16][2];
            af[0] = __float_as_uint(ps[(wrow + g    ) * PP_ + k0 + t4]);
            af[1] = __float_as_uint(ps[(wrow + 8 + g) * PP_ + k0 + t4]);
            af[2] = __float_as_uint(ps[(wrow + g    ) * PP_ + k0 + 4 + t4]);
            af[3] = __float_as_uint(ps[(wrow + 8 + g) * PP_ + k0 + 4 + t4]);
            #pragma unroll
            for (int j = 0; j < 16; j++) {
                bf[j][0] = __float_as_uint(vs[(k0 + t4    ) * VP_ + j * 8 + g]);
                bf[j][1] = __float_as_uint(vs[(k0 + 4 + t4) * VP_ + j * 8 + g]);
            }
            #pragma unroll
            for (int j = 0; j < 16; j++) mma_tf32(oa[j], af, bf[j]);
        }
    }

    float i0 = 1.f / l0, i1 = 1.f / l1;
    const int r0 = qbase + wrow + g;
    float* o0 = out + (size_t)r0 * H_ + h * VHD_;
    float* o1 = out + (size_t)(r0 + 8) * H_ + h * VHD_;
    #pragma unroll
    for (int j = 0; j < 16; j++) {
        int cc = j * 8 + 2 * t4;
        o0[cc]     = tf32r(oa[j][0] * i0);
        o0[cc + 1] = tf32r(oa[j][1] * i0);
        o1[cc]     = tf32r(oa[j][2] * i1);
        o1[cc + 1] = tf32r(oa[j][3] * i1);
    }
}

// ---------------- silu(gate) * up, in place into gate (tf32-rounded) ----------------
__global__ void silu_mul_kernel(float* __restrict__ g, const float* __restrict__ u, int n) {
    int i = blockIdx.x * blockDim.x + threadIdx.x;
    if (i < n) {
        float x = g[i];
        float s = x / (1.f + __expf(-x));
        g[i] = tf32r(s * u[i]);
    }
}

// ---------------- launcher ----------------
extern "C" void kernel_launch(void* const* d_in, const int* in_sizes, int n_in,
                              void* d_out, int out_size) {
    const float* hidden  = (const float*)d_in[0];
    const float* sinb    = (const float*)d_in[1];
    const float* cosb    = (const float*)d_in[2];
    const float* wq_a    = (const float*)d_in[3];
    const float* q_a_ln  = (const float*)d_in[4];
    const float* wq_b    = (const float*)d_in[5];
    const float* wkv_a   = (const float*)d_in[6];
    const float* kv_a_ln = (const float*)d_in[7];
    const float* wkv_b   = (const float*)d_in[8];
    const float* wo      = (const float*)d_in[9];
    const float* in_ln   = (const float*)d_in[10];
    const float* post_ln = (const float*)d_in[11];
    const float* w_gate  = (const float*)d_in[12];
    const float* w_up    = (const float*)d_in[13];
    const float* w_down  = (const float*)d_in[14];
    const int*   pos     = (const int*)d_in[15];
    float* outp = (float*)d_out;

    float *xnorm, *qlat, *qb, *ckv, *kvn, *kvb, *kpe, *attn, *hid2, *ynorm, *gate, *up;
    cudaGetSymbolAddress((void**)&xnorm, g_xnorm);
    cudaGetSymbolAddress((void**)&qlat,  g_qlat);
    cudaGetSymbolAddress((void**)&qb,    g_q);
    cudaGetSymbolAddress((void**)&ckv,   g_ckv);
    cudaGetSymbolAddress((void**)&kvn,   g_kvn);
    cudaGetSymbolAddress((void**)&kvb,   g_kv);
    cudaGetSymbolAddress((void**)&kpe,   g_kpe);
    cudaGetSymbolAddress((void**)&attn,  g_attn);
    cudaGetSymbolAddress((void**)&hid2,  g_hid2);
    cudaGetSymbolAddress((void**)&ynorm, g_ynorm);
    cudaGetSymbolAddress((void**)&gate,  g_gate);
    cudaGetSymbolAddress((void**)&up,    g_up);

    const size_t attn_smem = ATT_SMEM_FLOATS * sizeof(float);
    cudaFuncSetAttribute(attn_mma_kernel, cudaFuncAttributeMaxDynamicSharedMemorySize, (int)attn_smem);
    cudaFuncSetAttribute(gemm_tf32_big, cudaFuncAttributeMaxDynamicSharedMemorySize, GEMM2_SMEM);
    cudaFuncSetAttribute(gemm_tf32<64>, cudaFuncAttributeMaxDynamicSharedMemorySize, GEMM_SMEM_64);

    auto gemm128 = [&](const float* A, const float* B, const float* Cadd, float* C,
                       int M, int N, int K) {
        gemm_tf32_big<<<dim3(N / 128, M / 128), 128, GEMM2_SMEM>>>(A, B, Cadd, C, M, N, K);
    };
    auto gemm64 = [&](const float* A, const float* B, const float* Cadd, float* C,
                      int M, int N, int K) {
        gemm_tf32<64><<<dim3(N / 64, M / 128), 256, GEMM_SMEM_64>>>(A, B, Cadd, C, M, N, K);
    };

    // 1) x = rms(hidden, in_ln)
    rms_kernel<<<S_, 256>>>(hidden, in_ln, xnorm, H_, H_, H_);
    // 2) q_lat = x @ wq_a
    gemm128(xnorm, wq_a, nullptr, qlat, S_, QLR_, H_);
    // 3) q_lat = rms(q_lat, q_a_ln)
    rms_kernel<<<S_, 256>>>(qlat, q_a_ln, qlat, QLR_, QLR_, QLR_);
    // 4) q = q_lat @ wq_b
    gemm128(qlat, wq_b, nullptr, qb, S_, QDIM_, QLR_);
    // 5) ckv = x @ wkv_a   (N=576 -> BN=64)
    gemm64(xnorm, wkv_a, nullptr, ckv, S_, CKVD_, H_);
    // 6) kv_n = rms(ckv[:, :512], kv_a_ln)
    rms_kernel<<<S_, 256>>>(ckv, kv_a_ln, kvn, KVLR_, CKVD_, KVLR_);
    // 7) kv = kv_n @ wkv_b
    gemm128(kvn, wkv_b, nullptr, kvb, S_, KVDIM_, KVLR_);
    // 8) RoPE
    rope_kernel<<<S_, 128>>>(qb, ckv, kpe, cosb, sinb, pos);
    // 9) attention (tensor-core flash)
    attn_mma_kernel<<<dim3(S_/64, NH_), 128, attn_smem>>>(qb, kvb, kpe, attn);
    // 10) hid2 = hidden + attn @ wo
    gemm128(attn, wo, hidden, hid2, S_, H_, H_);
    // 11) y = rms(hid2, post_ln)
    rms_kernel<<<S_, 256>>>(hid2, post_ln, ynorm, H_, H_, H_);
    // 12) gate = y @ w_gate
    gemm128(ynorm, w_gate, nullptr, gate, S_, FF_, H_);
    // 13) up = y @ w_up
    gemm128(ynorm, w_up, nullptr, up, S_, FF_, H_);
    // 14) gate = silu(gate) * up
    {
        int n = S_ * FF_;
        silu_mul_kernel<<<(n + 255) / 256, 256>>>(gate, up, n);
    }
    // 15) out = hid2 + gate @ w_down
    gemm128(gate, w_down, hid2, outp, S_, H_, FF_);
}